// round 3
// baseline (speedup 1.0000x reference)
#include <cuda_runtime.h>

#define SEQ   2048          // B * CK
#define CKD   128
#define NSEQ  8192
#define W3    (128*128*128)

// ---------------- static device scratch (no allocations allowed) ----------------
__device__ float  g_xt[SEQ * NSEQ];      // transposed input x0 (B,CK,N); later recon buf A
__device__ float2 g_z  [SEQ * 4096];     // packed d + i*s per level; later recon buf B
__device__ float  g_x0 [SEQ * 4096];     // smooth coeffs, odd levels (x1, x3, ...)
__device__ float  g_x1 [SEQ * 2048];     // smooth coeffs, even levels (x2, x4, ...)
__device__ float2 g_Df [128 * SEQ];      // (mode, b, i) spectra of d
__device__ float2 g_Sf [128 * SEQ];      // (mode, b, i) spectra of s
__device__ float2 g_pud[512 * SEQ];      // partial UdF per i-chunk
__device__ float2 g_pus[512 * SEQ];      // partial UsF per i-chunk
__device__ float  g_wt [6 * W3];         // weights transposed to (w, mode, i, o)
__device__ float  g_Ud [SEQ * 8191];     // stored detail outputs, all levels
__device__ float  g_Us [SEQ * 8191];     // stored smooth outputs, all levels

// ---------------- input transpose: (B,N,C,K) -> (B, CK, N) ----------------
__global__ void k_tin(const float* __restrict__ x) {
    __shared__ float tile[32][129];
    int b  = blockIdx.x >> 8;            // 256 n-tiles per batch
    int n0 = (blockIdx.x & 255) << 5;
    const float* src = x + ((size_t)b * NSEQ + n0) * CKD;
    for (int idx = threadIdx.x; idx < 32 * 128; idx += blockDim.x) {
        int r = idx >> 7, cc = idx & 127;
        tile[r][cc] = src[(size_t)r * CKD + cc];
    }
    __syncthreads();
    float* dst = g_xt + (size_t)b * CKD * NSEQ + n0;
    for (int idx = threadIdx.x; idx < 32 * 128; idx += blockDim.x) {
        int ck = idx >> 5, j = idx & 31;
        dst[(size_t)ck * NSEQ + j] = tile[j][ck];
    }
}

// ---------------- weight transpose: (i,o,mode) -> (mode,i,o), per weight w ----------------
__global__ void k_wt(const float* __restrict__ wAr, const float* __restrict__ wAi,
                     const float* __restrict__ wBr, const float* __restrict__ wBi,
                     const float* __restrict__ wCr, const float* __restrict__ wCi) {
    __shared__ float tile[32][33];
    int w = blockIdx.z;
    int i = blockIdx.y;
    int ot = (blockIdx.x >> 2) << 5;     // o-tile base
    int mt = (blockIdx.x & 3) << 5;      // mode-tile base
    const float* src;
    switch (w) {
        case 0: src = wAr; break; case 1: src = wAi; break;
        case 2: src = wBr; break; case 3: src = wBi; break;
        case 4: src = wCr; break; default: src = wCi; break;
    }
    int tx = threadIdx.x, ty = threadIdx.y;     // (32, 8)
    #pragma unroll
    for (int j = 0; j < 32; j += 8)
        tile[ty + j][tx] = src[((size_t)i * 128 + ot + ty + j) * 128 + mt + tx];
    __syncthreads();
    float* dst = g_wt + (size_t)w * W3;
    #pragma unroll
    for (int j = 0; j < 32; j += 8)
        dst[((size_t)(mt + ty + j) * 128 + i) * 128 + ot + tx] = tile[tx][ty + j];
}

// ---------------- decompose: filter bank + pack z = d + i*s ----------------
__global__ void k_dec(const float* __restrict__ xin, int m,
                      float* __restrict__ xnext,
                      const float* __restrict__ ecs, const float* __restrict__ ecd) {
    int id = blockIdx.x * blockDim.x + threadIdx.x;
    if (id >= 512 * m) return;
    int t = id % m;
    int bc = id / m;                 // b*32 + c
    int row0 = bc * 4;               // == b*128 + c*4
    int n = 2 * m;
    float xa[8];
    #pragma unroll
    for (int k = 0; k < 4; k++) {
        const float* p = xin + (size_t)(row0 + k) * n + 2 * t;
        xa[k]     = p[0];            // even sample
        xa[4 + k] = p[1];            // odd sample
    }
    #pragma unroll
    for (int kp = 0; kp < 4; kp++) {
        float d = 0.f, s = 0.f;
        #pragma unroll
        for (int j = 0; j < 8; j++) {
            d += xa[j] * __ldg(&ecd[j * 4 + kp]);
            s += xa[j] * __ldg(&ecs[j * 4 + kp]);
        }
        size_t o = (size_t)(row0 + kp) * m + t;
        g_z[o] = make_float2(d, s);
        xnext[o] = s;
    }
}

// ---------------- in-place radix-2 FFT on shared memory ----------------
__device__ __forceinline__ void fft_sm(float2* sb, int m, int logm, float sgn) {
    int T = blockDim.x;
    for (int st = 1; st <= logm; st++) {
        int half = 1 << (st - 1);
        float scale = sgn * 6.283185307179586f / (float)(1 << st);
        for (int idx = threadIdx.x; idx < (m >> 1); idx += T) {
            int j = idx & (half - 1);
            int pos = ((idx >> (st - 1)) << st) + j;
            float sw, cw;
            sincosf(scale * (float)j, &sw, &cw);
            float2 u = sb[pos], v = sb[pos + half];
            float2 tv = make_float2(v.x * cw - v.y * sw, v.x * sw + v.y * cw);
            sb[pos]        = make_float2(u.x + tv.x, u.y + tv.y);
            sb[pos + half] = make_float2(u.x - tv.x, u.y - tv.y);
        }
        __syncthreads();
    }
}

// ---------------- forward FFT of packed z, split into Df / Sf ----------------
__global__ void k_fftf(int m, int logm, int l) {
    extern __shared__ float2 sb[];
    int s = blockIdx.x;
    int T = blockDim.x;
    const float2* zin = g_z + (size_t)s * m;
    for (int t = threadIdx.x; t < m; t += T) {
        int r = logm ? (int)(__brev((unsigned)t) >> (32 - logm)) : 0;
        sb[r] = zin[t];
    }
    __syncthreads();
    fft_sm(sb, m, logm, -1.0f);
    for (int k = threadIdx.x; k < l; k += T) {
        float2 Zk = sb[k];
        float2 Zm = sb[(m - k) & (m - 1)];
        // Df = (Z[k] + conj(Z[m-k]))/2 ; Sf = -i*(Z[k] - conj(Z[m-k]))/2
        float2 Df = make_float2(0.5f * (Zk.x + Zm.x), 0.5f * (Zk.y - Zm.y));
        float2 Sf = make_float2(0.5f * (Zk.y + Zm.y), 0.5f * (Zm.x - Zk.x));
        g_Df[(size_t)k * SEQ + s] = Df;
        g_Sf[(size_t)k * SEQ + s] = Sf;
    }
}

// ---------------- per-mode complex channel mixing (partial over i-chunk) ----------------
__global__ void __launch_bounds__(128) k_mix(int l, int ilen) {
    __shared__ float2 sdf[16][32], ssf[16][32];
    int mode = blockIdx.x, ch = blockIdx.y;
    int i0 = ch * ilen;
    int cnt = 16 * ilen;
    for (int idx = threadIdx.x; idx < cnt; idx += 128) {
        int bb = idx / ilen, ii = idx - bb * ilen;
        size_t src = (size_t)mode * SEQ + bb * 128 + i0 + ii;
        sdf[bb][ii] = g_Df[src];
        ssf[bb][ii] = g_Sf[src];
    }
    __syncthreads();
    int o = threadIdx.x;
    float udr[16], udi[16], usr[16], usi[16];
    #pragma unroll
    for (int b = 0; b < 16; b++) { udr[b] = udi[b] = usr[b] = usi[b] = 0.f; }
    for (int ii = 0; ii < ilen; ii++) {
        size_t widx = ((size_t)mode * 128 + (i0 + ii)) * 128 + o;
        float ar = g_wt[widx],          ai = g_wt[W3 + widx];
        float br = g_wt[2 * W3 + widx], bi = g_wt[3 * W3 + widx];
        float cr = g_wt[4 * W3 + widx], ci = g_wt[5 * W3 + widx];
        #pragma unroll
        for (int b = 0; b < 16; b++) {
            float2 df = sdf[b][ii], sf = ssf[b][ii];
            udr[b] += df.x * ar - df.y * ai + sf.x * br - sf.y * bi;
            udi[b] += df.x * ai + df.y * ar + sf.x * bi + sf.y * br;
            usr[b] += df.x * cr - df.y * ci;
            usi[b] += df.x * ci + df.y * cr;
        }
    }
    size_t base = ((size_t)ch * l + mode) * SEQ + o;
    #pragma unroll
    for (int b = 0; b < 16; b++) {
        g_pud[base + b * 128] = make_float2(udr[b], udi[b]);
        g_pus[base + b * 128] = make_float2(usr[b], usi[b]);
    }
}

// ---------------- inverse FFT: sum partials, assemble Hermitian spectrum, store Ud/Us ----------------
__global__ void k_ffti(int m, int logm, int l, int nch, size_t off) {
    extern __shared__ float2 sb[];
    int s = blockIdx.x;
    int T = blockDim.x;
    for (int k = threadIdx.x; k < m; k += T) {
        float2 Z = make_float2(0.f, 0.f);
        int j = -1, cj = 0;
        if (k < l) { j = k; }
        else { int jm = m - k; if (jm < l) { j = jm; cj = 1; } }
        if (j >= 0) {
            float udx = 0.f, udy = 0.f, usx = 0.f, usy = 0.f;
            for (int ch = 0; ch < nch; ch++) {
                size_t base = ((size_t)ch * l + j) * SEQ + s;
                float2 a = g_pud[base]; udx += a.x; udy += a.y;
                float2 c = g_pus[base]; usx += c.x; usy += c.y;
            }
            if (!cj) {
                if (j == 0 || 2 * j == m) Z = make_float2(udx, usx);  // DC/Nyquist: real parts only
                else                      Z = make_float2(udx - usy, udy + usx);
            } else {
                Z = make_float2(udx + usy, usx - udy);                 // conj(Gd) + i*conj(Gs)
            }
        }
        int r = logm ? (int)(__brev((unsigned)k) >> (32 - logm)) : 0;
        sb[r] = Z;
    }
    __syncthreads();
    fft_sm(sb, m, logm, +1.0f);
    float inv = 1.0f / (float)m;
    float* pud = g_Ud + off + (size_t)s * m;
    float* pus = g_Us + off + (size_t)s * m;
    for (int t = threadIdx.x; t < m; t += T) {
        float2 v = sb[t];
        pud[t] = v.x * inv;
        pus[t] = v.y * inv;
    }
}

// ---------------- coarsest-scale T0 linear map ----------------
__global__ void k_t0(const float* __restrict__ xin, const float* __restrict__ w,
                     const float* __restrict__ bias, float* __restrict__ out) {
    int id = blockIdx.x * blockDim.x + threadIdx.x;
    if (id >= 512) return;
    float v[4];
    #pragma unroll
    for (int k = 0; k < 4; k++) v[k] = xin[id * 4 + k];
    #pragma unroll
    for (int kp = 0; kp < 4; kp++) {
        float a = __ldg(&bias[kp]);
        #pragma unroll
        for (int k = 0; k < 4; k++) a += v[k] * __ldg(&w[kp * 4 + k]);
        out[id * 4 + kp] = a;
    }
}

// ---------------- reconstruction: x += Us; [x|Ud] @ rc_e / rc_o, interleave ----------------
__global__ void k_rec(const float* __restrict__ rin, int m, size_t off,
                      float* __restrict__ rout, int final_,
                      const float* __restrict__ rce, const float* __restrict__ rco) {
    int id = blockIdx.x * blockDim.x + threadIdx.x;
    if (id >= 512 * m) return;
    int t = id % m;
    int bc = id / m;
    int row0 = bc * 4;
    float xs[4], ud[4];
    #pragma unroll
    for (int k = 0; k < 4; k++) {
        size_t o = (size_t)(row0 + k) * m + t;
        xs[k] = rin[o] + g_Us[off + o];
        ud[k] = g_Ud[off + o];
    }
    float ev[4], ov[4];
    #pragma unroll
    for (int kp = 0; kp < 4; kp++) {
        float e = 0.f, o = 0.f;
        #pragma unroll
        for (int j = 0; j < 4; j++) {
            e += xs[j] * __ldg(&rce[j * 4 + kp]) + ud[j] * __ldg(&rce[(4 + j) * 4 + kp]);
            o += xs[j] * __ldg(&rco[j * 4 + kp]) + ud[j] * __ldg(&rco[(4 + j) * 4 + kp]);
        }
        ev[kp] = e; ov[kp] = o;
    }
    if (final_) {
        int b = bc >> 5, c = bc & 31;
        float* p0 = rout + (((size_t)b * NSEQ + 2 * t) * 32 + c) * 4;
        float* p1 = p0 + 128;
        #pragma unroll
        for (int kp = 0; kp < 4; kp++) { p0[kp] = ev[kp]; p1[kp] = ov[kp]; }
    } else {
        #pragma unroll
        for (int kp = 0; kp < 4; kp++) {
            size_t o = (size_t)(row0 + kp) * (2 * m);
            rout[o + 2 * t]     = ev[kp];
            rout[o + 2 * t + 1] = ov[kp];
        }
    }
}

// ---------------- host orchestration ----------------
extern "C" void kernel_launch(void* const* d_in, const int* in_sizes, int n_in,
                              void* d_out, int out_size) {
    const float* x   = (const float*)d_in[0];
    const float* wAr = (const float*)d_in[1];
    const float* wAi = (const float*)d_in[2];
    const float* wBr = (const float*)d_in[3];
    const float* wBi = (const float*)d_in[4];
    const float* wCr = (const float*)d_in[5];
    const float* wCi = (const float*)d_in[6];
    const float* ecs = (const float*)d_in[7];
    const float* ecd = (const float*)d_in[8];
    const float* rce = (const float*)d_in[9];
    const float* rco = (const float*)d_in[10];
    const float* t0w = (const float*)d_in[11];
    const float* t0b = (const float*)d_in[12];
    float* out = (float*)d_out;

    float *p_xt, *p_x0, *p_x1; float2* p_z;
    cudaGetSymbolAddress((void**)&p_xt, g_xt);
    cudaGetSymbolAddress((void**)&p_x0, g_x0);
    cudaGetSymbolAddress((void**)&p_x1, g_x1);
    cudaGetSymbolAddress((void**)&p_z,  g_z);

    k_tin<<<16 * 256, 256>>>(x);
    k_wt<<<dim3(16, 128, 6), dim3(32, 8)>>>(wAr, wAi, wBr, wBi, wCr, wCi);

    size_t cum = 0;
    for (int lev = 0; lev < 13; lev++) {
        int m = (NSEQ >> lev) >> 1;
        int logm = 12 - lev;
        int l = (m / 2 + 1 < 128) ? (m / 2 + 1) : 128;
        const float* xin = (lev == 0) ? p_xt : ((lev & 1) ? p_x0 : p_x1);
        float* xnext = (lev & 1) ? p_x1 : p_x0;

        int tot = 512 * m;
        k_dec<<<(tot + 255) / 256, 256>>>(xin, m, xnext, ecs, ecd);

        int T = (m >= 512) ? 256 : ((m >= 64) ? (m >> 1) : 32);
        k_fftf<<<SEQ, T, m * sizeof(float2)>>>(m, logm, l);

        int nch = (l >= 32) ? 4 : 16;
        int ilen = 128 / nch;
        k_mix<<<dim3(l, nch), 128>>>(l, ilen);

        k_ffti<<<SEQ, T, m * sizeof(float2)>>>(m, logm, l, nch, cum * (size_t)SEQ);
        cum += m;
    }

    // coarsest x (length 1) lives in g_x0 (written by level 12)
    k_t0<<<2, 256>>>(p_x0, t0w, t0b, p_xt);

    float* bufA = p_xt;
    float* bufB = (float*)p_z;
    float* cur = bufA;
    for (int lev = 12; lev >= 0; lev--) {
        int m = (NSEQ >> lev) >> 1;
        cum -= m;
        size_t off = cum * (size_t)SEQ;
        int fin = (lev == 0);
        float* rout = fin ? out : ((cur == bufA) ? bufB : bufA);
        int tot = 512 * m;
        k_rec<<<(tot + 255) / 256, 256>>>(cur, m, off, rout, fin, rce, rco);
        if (!fin) cur = rout;
    }
    (void)in_sizes; (void)n_in; (void)out_size;
}